// round 12
// baseline (speedup 1.0000x reference)
#include <cuda_runtime.h>
#include <cstdint>

#define NN     8
#define CC     21
#define HWP    262144      // 512*512
#define NQUAD  (HWP / 4)   // 65536 quads per sample
#define OLDCL  16
#define IGN    255
#define NCLS   6
#define GX     64          // 64 blocks/sample * 1024 quads/block = 65536 quads
#define TPB    256

__device__ float        g_part[NN * 16];
__device__ unsigned int g_done = 0;

__device__ __forceinline__ float lg2f(float x) {
    float y; asm("lg2.approx.f32 %0,%1;" : "=f"(y) : "f"(x)); return y;
}

__global__ __launch_bounds__(TPB) void fused_k(const float* __restrict__ in,
                                               const int* __restrict__ tg,
                                               float* __restrict__ out) {
    const float LN2 = 0.6931471805599453f;
    int n = blockIdx.y;
    const float* base = in + (size_t)n * CC * HWP;
    const int*   t    = tg + (size_t)n * HWP;

    float accT[NCLS] = {0, 0, 0, 0, 0, 0};
    unsigned long long hcnt = 0ull;   // 7 x 9-bit counters: slots 0..5 classes, 6 invalid
                                      // (max 4 iters * 4 px = 16 counts < 511: safe)
    // contiguous tile per block: quads [bx*1024, (bx+1)*1024), iter advances by TPB
    int g0 = blockIdx.x * (TPB * 4) + threadIdx.x;
#pragma unroll 1
    for (int i = 0; i < 4; i++) {
        int p = (g0 + i * TPB) * 4;
        int4 tv = *reinterpret_cast<const int4*>(t + p);

        float4 s = make_float4(0.f, 0.f, 0.f, 0.f);

        // ---- channels 0..15: two batches of 8 hoisted LDG.128 ----
#pragma unroll
        for (int b = 0; b < 2; b++) {
            float4 xv[8];
#pragma unroll
            for (int j = 0; j < 8; j++)
                xv[j] = __ldcs(reinterpret_cast<const float4*>(
                    base + (size_t)(b * 8 + j) * HWP + p));
#pragma unroll
            for (int j = 0; j < 8; j++) {
                s.x += __expf(xv[j].x);
                s.y += __expf(xv[j].y);
                s.z += __expf(xv[j].z);
                s.w += __expf(xv[j].w);
            }
        }
        float4 s16 = s;                              // sum over channels 0..15

        // ---- channels 16..20: batch of 5, with label-select tracking ----
        float4 sel = make_float4(0.f, 0.f, 0.f, 0.f);
        {
            float4 xv[5];
#pragma unroll
            for (int j = 0; j < 5; j++)
                xv[j] = __ldcs(reinterpret_cast<const float4*>(
                    base + (size_t)(OLDCL + j) * HWP + p));
#pragma unroll
            for (int j = 0; j < 5; j++) {
                int c = OLDCL + j;
                s.x += __expf(xv[j].x);
                s.y += __expf(xv[j].y);
                s.z += __expf(xv[j].z);
                s.w += __expf(xv[j].w);
                sel.x = (c == tv.x) ? xv[j].x : sel.x;
                sel.y = (c == tv.y) ? xv[j].y : sel.y;
                sel.z = (c == tv.z) ? xv[j].z : sel.z;
                sel.w = (c == tv.w) ? xv[j].w : sel.w;
            }
        }

        // ---- per-pixel finalize: packed-counter histogram + 6-way T scatter ----
        int   tj[4] = {tv.x, tv.y, tv.z, tv.w};
        float sv[4] = {s.x, s.y, s.z, s.w};
        float qv[4] = {s16.x, s16.y, s16.z, s16.w};
        float se[4] = {sel.x, sel.y, sel.z, sel.w};
#pragma unroll
        for (int px = 0; px < 4; px++) {
            int idx  = (tj[px] < OLDCL) ? 0 : (tj[px] - (OLDCL - 1)); // 0..5, big if IGN
            int code = (idx > 6) ? 6 : idx;                            // 6 = invalid
            hcnt += 1ull << (9 * code);
            float a  = lg2f(sv[px]);
            float lp = (idx == 0) ? ((lg2f(qv[px]) - a) * LN2)
                                  : fmaf(-LN2, a, se[px]);
#pragma unroll
            for (int k = 0; k < NCLS; k++)
                if (idx == k) accT[k] += lp;
        }
    }

    // ---- block reduction of 13 values (6 T + 6 H + vcount) ----
    float vals[13];
    float vcf = 0.0f;
#pragma unroll
    for (int k = 0; k < NCLS; k++) {
        vals[k] = accT[k];
        float c = (float)((hcnt >> (9 * k)) & 511ull);
        vals[k + NCLS] = c;
        vcf += c;
    }
    vals[12] = vcf;

    __shared__ float sh[8][13];
    int lane = threadIdx.x & 31;
    int wid  = threadIdx.x >> 5;
#pragma unroll
    for (int k = 0; k < 13; k++) {
        float v = vals[k];
        v += __shfl_down_sync(0xffffffffu, v, 16);
        v += __shfl_down_sync(0xffffffffu, v, 8);
        v += __shfl_down_sync(0xffffffffu, v, 4);
        v += __shfl_down_sync(0xffffffffu, v, 2);
        v += __shfl_down_sync(0xffffffffu, v, 1);
        if (lane == 0) sh[wid][k] = v;
    }
    __syncthreads();
    if (wid == 0) {
#pragma unroll
        for (int k = 0; k < 13; k++) {
            float v = (lane < 8) ? sh[lane][k] : 0.0f;
            v += __shfl_down_sync(0xffffffffu, v, 4);
            v += __shfl_down_sync(0xffffffffu, v, 2);
            v += __shfl_down_sync(0xffffffffu, v, 1);
            if (lane == 0) atomicAdd(&g_part[n * 16 + k], v);
        }
    }

    // ---- last-block finalize ----
    __shared__ int is_last;
    __threadfence();
    if (threadIdx.x == 0) {
        unsigned int v = atomicAdd(&g_done, 1u);
        is_last = (v == (unsigned)(GX * NN) - 1u) ? 1 : 0;
    }
    __syncthreads();
    if (!is_last) return;

    __threadfence();
    if (wid == 0) {
        float num = 0.0f, den = 0.0f;
        if (lane < NN) {
            float T[NCLS], H[NCLS];
#pragma unroll
            for (int k = 0; k < NCLS; k++) {
                T[k] = __ldcg(&g_part[lane * 16 + k]);
                H[k] = __ldcg(&g_part[lane * 16 + NCLS + k]);
            }
            float vcn = __ldcg(&g_part[lane * 16 + 12]);
            float hs[NCLS], S = 0.0f;
#pragma unroll
            for (int k = 0; k < NCLS; k++) {
                hs[k] = (H[k] == 0.0f) ? 1.0f : H[k];   // empty classes -> 1 (RATIO=1)
                S += hs[k];
            }
            float c = 0.0f;
#pragma unroll
            for (int k = 0; k < NCLS; k++) c += (S / hs[k]) * T[k];   // weight = S/h
            num = c;
            den = vcn;
        }
        num += __shfl_down_sync(0xffffffffu, num, 4);
        den += __shfl_down_sync(0xffffffffu, den, 4);
        num += __shfl_down_sync(0xffffffffu, num, 2);
        den += __shfl_down_sync(0xffffffffu, den, 2);
        num += __shfl_down_sync(0xffffffffu, num, 1);
        den += __shfl_down_sync(0xffffffffu, den, 1);
        if (lane == 0) out[0] = -num / den;
    }
    __syncthreads();
    if (threadIdx.x < NN * 16) g_part[threadIdx.x] = 0.0f;
    if (threadIdx.x == 0)      g_done = 0;
}

extern "C" void kernel_launch(void* const* d_in, const int* in_sizes, int n_in,
                              void* d_out, int out_size) {
    const float* in;
    const int*   tg;
    if (in_sizes[0] > in_sizes[1]) {
        in = (const float*)d_in[0];
        tg = (const int*)d_in[1];
    } else {
        in = (const float*)d_in[1];
        tg = (const int*)d_in[0];
    }
    dim3 grid(GX, NN);
    fused_k<<<grid, TPB>>>(in, tg, (float*)d_out);
}

// round 13
// speedup vs baseline: 1.0009x; 1.0009x over previous
#include <cuda_runtime.h>
#include <cstdint>

#define NN     8
#define CC     21
#define HWP    262144      // 512*512
#define NQUAD  (HWP / 4)   // 65536 quads per sample
#define OLDCL  16
#define IGN    255
#define NCLS   6
#define GX     32          // 32 blocks/sample * 512 thr = 16384 thr -> exactly 4 iters
#define TPB    512

__device__ float        g_part[NN * 16];
__device__ unsigned int g_done = 0;

__device__ __forceinline__ float lg2f(float x) {
    float y; asm("lg2.approx.f32 %0,%1;" : "=f"(y) : "f"(x)); return y;
}

__global__ __launch_bounds__(TPB) void fused_k(const float* __restrict__ in,
                                               const int* __restrict__ tg,
                                               float* __restrict__ out) {
    const float LN2 = 0.6931471805599453f;
    int n = blockIdx.y;
    const float* base = in + (size_t)n * CC * HWP;
    const int*   t    = tg + (size_t)n * HWP;

    float accT[NCLS] = {0, 0, 0, 0, 0, 0};
    unsigned long long hcnt = 0ull;   // 7 x 9-bit counters: slots 0..5 classes, 6 invalid
                                      // (max 4 iters * 4 px = 16 counts < 511: safe)
    const int stride = GX * TPB;      // 16384
    int g0 = blockIdx.x * TPB + threadIdx.x;
#pragma unroll 1
    for (int i = 0; i < 4; i++) {
        int p = (g0 + i * stride) * 4;
        int4 tv = *reinterpret_cast<const int4*>(t + p);

        float4 s = make_float4(0.f, 0.f, 0.f, 0.f);

        // ---- channels 0..15: two batches of 8 hoisted LDG.128 ----
#pragma unroll
        for (int b = 0; b < 2; b++) {
            float4 xv[8];
#pragma unroll
            for (int j = 0; j < 8; j++)
                xv[j] = __ldcs(reinterpret_cast<const float4*>(
                    base + (size_t)(b * 8 + j) * HWP + p));
#pragma unroll
            for (int j = 0; j < 8; j++) {
                s.x += __expf(xv[j].x);
                s.y += __expf(xv[j].y);
                s.z += __expf(xv[j].z);
                s.w += __expf(xv[j].w);
            }
        }
        float4 s16 = s;                              // sum over channels 0..15

        // ---- channels 16..20: batch of 5, with label-select tracking ----
        float4 sel = make_float4(0.f, 0.f, 0.f, 0.f);
        {
            float4 xv[5];
#pragma unroll
            for (int j = 0; j < 5; j++)
                xv[j] = __ldcs(reinterpret_cast<const float4*>(
                    base + (size_t)(OLDCL + j) * HWP + p));
#pragma unroll
            for (int j = 0; j < 5; j++) {
                int c = OLDCL + j;
                s.x += __expf(xv[j].x);
                s.y += __expf(xv[j].y);
                s.z += __expf(xv[j].z);
                s.w += __expf(xv[j].w);
                sel.x = (c == tv.x) ? xv[j].x : sel.x;
                sel.y = (c == tv.y) ? xv[j].y : sel.y;
                sel.z = (c == tv.z) ? xv[j].z : sel.z;
                sel.w = (c == tv.w) ? xv[j].w : sel.w;
            }
        }

        // ---- per-pixel finalize: packed-counter histogram + 6-way T scatter ----
        int   tj[4] = {tv.x, tv.y, tv.z, tv.w};
        float sv[4] = {s.x, s.y, s.z, s.w};
        float qv[4] = {s16.x, s16.y, s16.z, s16.w};
        float se[4] = {sel.x, sel.y, sel.z, sel.w};
#pragma unroll
        for (int px = 0; px < 4; px++) {
            int idx  = (tj[px] < OLDCL) ? 0 : (tj[px] - (OLDCL - 1)); // 0..5, big if IGN
            int code = (idx > 6) ? 6 : idx;                            // 6 = invalid
            hcnt += 1ull << (9 * code);
            float a  = lg2f(sv[px]);
            float lp = (idx == 0) ? ((lg2f(qv[px]) - a) * LN2)
                                  : fmaf(-LN2, a, se[px]);
#pragma unroll
            for (int k = 0; k < NCLS; k++)
                if (idx == k) accT[k] += lp;
        }
    }

    // ---- block reduction of 13 values (6 T + 6 H + vcount) ----
    float vals[13];
    float vcf = 0.0f;
#pragma unroll
    for (int k = 0; k < NCLS; k++) {
        vals[k] = accT[k];
        float c = (float)((hcnt >> (9 * k)) & 511ull);
        vals[k + NCLS] = c;
        vcf += c;
    }
    vals[12] = vcf;

    __shared__ float sh[16][13];
    int lane = threadIdx.x & 31;
    int wid  = threadIdx.x >> 5;
#pragma unroll
    for (int k = 0; k < 13; k++) {
        float v = vals[k];
        v += __shfl_down_sync(0xffffffffu, v, 16);
        v += __shfl_down_sync(0xffffffffu, v, 8);
        v += __shfl_down_sync(0xffffffffu, v, 4);
        v += __shfl_down_sync(0xffffffffu, v, 2);
        v += __shfl_down_sync(0xffffffffu, v, 1);
        if (lane == 0) sh[wid][k] = v;
    }
    __syncthreads();
    if (wid == 0) {
#pragma unroll
        for (int k = 0; k < 13; k++) {
            float v = (lane < 16) ? sh[lane][k] : 0.0f;
            v += __shfl_down_sync(0xffffffffu, v, 8);
            v += __shfl_down_sync(0xffffffffu, v, 4);
            v += __shfl_down_sync(0xffffffffu, v, 2);
            v += __shfl_down_sync(0xffffffffu, v, 1);
            if (lane == 0) atomicAdd(&g_part[n * 16 + k], v);
        }
    }

    // ---- last-block finalize ----
    __shared__ int is_last;
    __threadfence();
    if (threadIdx.x == 0) {
        unsigned int v = atomicAdd(&g_done, 1u);
        is_last = (v == (unsigned)(GX * NN) - 1u) ? 1 : 0;
    }
    __syncthreads();
    if (!is_last) return;

    __threadfence();
    if (wid == 0) {
        float num = 0.0f, den = 0.0f;
        if (lane < NN) {
            float T[NCLS], H[NCLS];
#pragma unroll
            for (int k = 0; k < NCLS; k++) {
                T[k] = __ldcg(&g_part[lane * 16 + k]);
                H[k] = __ldcg(&g_part[lane * 16 + NCLS + k]);
            }
            float vcn = __ldcg(&g_part[lane * 16 + 12]);
            float hs[NCLS], S = 0.0f;
#pragma unroll
            for (int k = 0; k < NCLS; k++) {
                hs[k] = (H[k] == 0.0f) ? 1.0f : H[k];   // empty classes -> 1 (RATIO=1)
                S += hs[k];
            }
            float c = 0.0f;
#pragma unroll
            for (int k = 0; k < NCLS; k++) c += (S / hs[k]) * T[k];   // weight = S/h
            num = c;
            den = vcn;
        }
        num += __shfl_down_sync(0xffffffffu, num, 4);
        den += __shfl_down_sync(0xffffffffu, den, 4);
        num += __shfl_down_sync(0xffffffffu, num, 2);
        den += __shfl_down_sync(0xffffffffu, den, 2);
        num += __shfl_down_sync(0xffffffffu, num, 1);
        den += __shfl_down_sync(0xffffffffu, den, 1);
        if (lane == 0) out[0] = -num / den;
    }
    __syncthreads();
    if (threadIdx.x < NN * 16) g_part[threadIdx.x] = 0.0f;
    if (threadIdx.x == 0)      g_done = 0;
}

extern "C" void kernel_launch(void* const* d_in, const int* in_sizes, int n_in,
                              void* d_out, int out_size) {
    const float* in;
    const int*   tg;
    if (in_sizes[0] > in_sizes[1]) {
        in = (const float*)d_in[0];
        tg = (const int*)d_in[1];
    } else {
        in = (const float*)d_in[1];
        tg = (const int*)d_in[0];
    }
    dim3 grid(GX, NN);
    fused_k<<<grid, TPB>>>(in, tg, (float*)d_out);
}